// round 1
// baseline (speedup 1.0000x reference)
#include <cuda_runtime.h>
#include <math.h>
#include <stdint.h>

#define N_NODES 50000
#define N_EDGES 800000
#define HID     128
#define OUT_CH  64
#define N_LAYERS 4
#define CATW    (HID * N_LAYERS)   // 512

// ---------------- device scratch (no runtime allocation allowed) ----------------
__device__ float g_x0[(size_t)N_NODES * HID];      // input projection output
__device__ float g_h[(size_t)N_NODES * HID];       // per-layer GEMM output
__device__ float g_cat[(size_t)N_NODES * CATW];    // concatenated layer outputs
__device__ int   g_degi[N_NODES];
__device__ float g_dinv[N_NODES];
__device__ float g_norm[N_EDGES];
__device__ int   g_src[N_EDGES];
__device__ int   g_dst[N_EDGES];
__device__ int   g_is64;

// ---------------- edge dtype detection (int64 vs int32) ----------------
__global__ void detect_kernel(const void* ei) {
    const long long* p = (const long long*)ei;
    int bad = 0;
    for (int i = threadIdx.x; i < 1024; i += blockDim.x) {
        long long v = p[i];
        if (v < 0 || v >= (long long)N_NODES) bad = 1;
    }
    bad = __syncthreads_or(bad);
    if (threadIdx.x == 0) g_is64 = bad ? 0 : 1;
}

__global__ void convert_kernel(const void* ei) {
    int e = blockIdx.x * blockDim.x + threadIdx.x;
    if (e >= N_EDGES) return;
    int s, d;
    if (g_is64) {
        const long long* p = (const long long*)ei;
        s = (int)p[e];
        d = (int)p[N_EDGES + e];
    } else {
        const int* p = (const int*)ei;
        s = p[e];
        d = p[N_EDGES + e];
    }
    g_src[e] = s;
    g_dst[e] = d;
}

// ---------------- degree / norm ----------------
__global__ void deg_init_kernel() {
    int v = blockIdx.x * blockDim.x + threadIdx.x;
    if (v < N_NODES) g_degi[v] = 1;   // self loop
}

__global__ void deg_count_kernel() {
    int e = blockIdx.x * blockDim.x + threadIdx.x;
    if (e < N_EDGES) atomicAdd(&g_degi[g_dst[e]], 1);
}

__global__ void norm_kernel() {
    int e = blockIdx.x * blockDim.x + threadIdx.x;
    if (e >= N_EDGES) return;
    float pd = (float)g_degi[g_src[e]] * (float)g_degi[g_dst[e]];
    g_norm[e] = 1.0f / sqrtf(pd);
}

__global__ void dinv_kernel() {
    int v = blockIdx.x * blockDim.x + threadIdx.x;
    if (v < N_NODES) g_dinv[v] = 1.0f / (float)g_degi[v];
}

// ---------------- SGEMM: C[M,NC] = A[M,K] @ W[NC,K]^T + bias, optional relu ----------------
template <int BM, int BN, int BK, int TM, int TN, bool RELU>
__global__ void sgemm_kernel(const float* __restrict__ A, int lda,
                             const float* __restrict__ W,
                             const float* __restrict__ bias,
                             float* __restrict__ C, int ldc,
                             int M, int K) {
    constexpr int NT = (BM / TM) * (BN / TN);
    const int m0 = blockIdx.x * BM;
    const int n0 = blockIdx.y * BN;

    __shared__ __align__(16) float As[BK * BM];
    __shared__ __align__(16) float Bs[BK * BN];

    float acc[TM][TN];
#pragma unroll
    for (int i = 0; i < TM; i++)
#pragma unroll
        for (int j = 0; j < TN; j++) acc[i][j] = 0.0f;

    const int tid  = threadIdx.x;
    const int tRow = tid / (BN / TN);
    const int tCol = tid % (BN / TN);

    for (int k0 = 0; k0 < K; k0 += BK) {
        // load A tile transposed: As[k][m]
#pragma unroll
        for (int idx = tid * 4; idx < BM * BK; idx += NT * 4) {
            int row = idx / BK, col = idx % BK;
            float4 v = make_float4(0.f, 0.f, 0.f, 0.f);
            if (m0 + row < M)
                v = *(const float4*)(A + (size_t)(m0 + row) * lda + k0 + col);
            As[(col + 0) * BM + row] = v.x;
            As[(col + 1) * BM + row] = v.y;
            As[(col + 2) * BM + row] = v.z;
            As[(col + 3) * BM + row] = v.w;
        }
        // load W tile transposed: Bs[k][n] = W[n0+n][k0+k]
#pragma unroll
        for (int idx = tid * 4; idx < BN * BK; idx += NT * 4) {
            int row = idx / BK, col = idx % BK;   // row = n, col = k
            float4 v = *(const float4*)(W + (size_t)(n0 + row) * K + k0 + col);
            Bs[(col + 0) * BN + row] = v.x;
            Bs[(col + 1) * BN + row] = v.y;
            Bs[(col + 2) * BN + row] = v.z;
            Bs[(col + 3) * BN + row] = v.w;
        }
        __syncthreads();

#pragma unroll
        for (int k = 0; k < BK; k++) {
            float4 a0 = *(const float4*)&As[k * BM + tRow * TM];
            float4 a1 = *(const float4*)&As[k * BM + tRow * TM + 4];
            float4 b0 = *(const float4*)&Bs[k * BN + tCol * TN];
            float4 b1 = *(const float4*)&Bs[k * BN + tCol * TN + 4];
            float rm[TM] = {a0.x, a0.y, a0.z, a0.w, a1.x, a1.y, a1.z, a1.w};
            float rn[TN] = {b0.x, b0.y, b0.z, b0.w, b1.x, b1.y, b1.z, b1.w};
#pragma unroll
            for (int i = 0; i < TM; i++)
#pragma unroll
                for (int j = 0; j < TN; j++) acc[i][j] += rm[i] * rn[j];
        }
        __syncthreads();
    }

    // epilogue
#pragma unroll
    for (int i = 0; i < TM; i++) {
        int m = m0 + tRow * TM + i;
        if (m >= M) break;
#pragma unroll
        for (int j = 0; j < TN; j += 4) {
            int n = n0 + tCol * TN + j;
            float4 r;
            r.x = acc[i][j + 0] + bias[n + 0];
            r.y = acc[i][j + 1] + bias[n + 1];
            r.z = acc[i][j + 2] + bias[n + 2];
            r.w = acc[i][j + 3] + bias[n + 3];
            if (RELU) {
                r.x = fmaxf(r.x, 0.f);
                r.y = fmaxf(r.y, 0.f);
                r.z = fmaxf(r.z, 0.f);
                r.w = fmaxf(r.w, 0.f);
            }
            *(float4*)(C + (size_t)m * ldc + n) = r;
        }
    }
}

// ---------------- aggregation ----------------
// init: out[v] = h[v] * (1/deg[v])   (self-loop contribution, overwrites slice)
__global__ void self_init_kernel(const float* __restrict__ h, float* __restrict__ cat_slice) {
    int t = blockIdx.x * blockDim.x + threadIdx.x;
    if (t >= N_NODES * 32) return;
    int v = t >> 5, q = t & 31;
    float4 hv = ((const float4*)(h + (size_t)v * HID))[q];
    float s = g_dinv[v];
    hv.x *= s; hv.y *= s; hv.z *= s; hv.w *= s;
    ((float4*)(cat_slice + (size_t)v * CATW))[q] = hv;
}

// scatter: one warp per edge, vector atomic adds into the cat slice
__global__ void scatter_kernel(const float* __restrict__ h, float* __restrict__ cat_slice) {
    int gt = blockIdx.x * blockDim.x + threadIdx.x;
    int e = gt >> 5, lane = gt & 31;
    if (e >= N_EDGES) return;
    int s = g_src[e], d = g_dst[e];
    float nm = g_norm[e];
    float4 v = ((const float4*)(h + (size_t)s * HID))[lane];
    float x = v.x * nm, y = v.y * nm, z = v.z * nm, w = v.w * nm;
    float* p = cat_slice + (size_t)d * CATW + lane * 4;
    asm volatile("red.global.add.v4.f32 [%0], {%1, %2, %3, %4};"
                 :: "l"(p), "f"(x), "f"(y), "f"(z), "f"(w)
                 : "memory");
}

__global__ void relu_slice_kernel(float* __restrict__ cat_slice) {
    int t = blockIdx.x * blockDim.x + threadIdx.x;
    if (t >= N_NODES * 32) return;
    int v = t >> 5, q = t & 31;
    float4* p = (float4*)(cat_slice + (size_t)v * CATW) + q;
    float4 x = *p;
    x.x = fmaxf(x.x, 0.f);
    x.y = fmaxf(x.y, 0.f);
    x.z = fmaxf(x.z, 0.f);
    x.w = fmaxf(x.w, 0.f);
    *p = x;
}

// ---------------- launch ----------------
extern "C" void kernel_launch(void* const* d_in, const int* in_sizes, int n_in,
                              void* d_out, int out_size) {
    const float* x     = (const float*)d_in[0];
    const void*  ei    = d_in[1];
    const float* W_in  = (const float*)d_in[2];
    const float* b_in  = (const float*)d_in[3];
    const float* Wc    = (const float*)d_in[4];
    const float* bc    = (const float*)d_in[5];
    const float* W_out = (const float*)d_in[6];
    const float* b_out = (const float*)d_in[7];
    float* out = (float*)d_out;

    float *x0, *h, *cat;
    cudaGetSymbolAddress((void**)&x0, g_x0);
    cudaGetSymbolAddress((void**)&h, g_h);
    cudaGetSymbolAddress((void**)&cat, g_cat);

    const int TB = 256;
    const int M = N_NODES;

    // edge preprocessing
    detect_kernel<<<1, 256>>>(ei);
    convert_kernel<<<(N_EDGES + TB - 1) / TB, TB>>>(ei);
    deg_init_kernel<<<(N_NODES + TB - 1) / TB, TB>>>();
    deg_count_kernel<<<(N_EDGES + TB - 1) / TB, TB>>>();
    norm_kernel<<<(N_EDGES + TB - 1) / TB, TB>>>();
    dinv_kernel<<<(N_NODES + TB - 1) / TB, TB>>>();

    // input projection + relu: x0 = relu(x @ W_in^T + b_in)
    {
        dim3 grid((M + 127) / 128, 1);
        sgemm_kernel<128, 128, 8, 8, 8, true><<<grid, 256>>>(x, HID, W_in, b_in, x0, HID, M, HID);
    }

    const int vthreads = N_NODES * 32;
    for (int L = 0; L < N_LAYERS; L++) {
        const float* A = (L == 0) ? x0 : (cat + (size_t)(L - 1) * HID);
        int lda = (L == 0) ? HID : CATW;
        // h = A @ Wc[L]^T + bc[L]
        dim3 grid((M + 127) / 128, 1);
        sgemm_kernel<128, 128, 8, 8, 8, false><<<grid, 256>>>(
            A, lda, Wc + (size_t)L * HID * HID, bc + (size_t)L * HID, h, HID, M, HID);

        float* slice = cat + (size_t)L * HID;
        self_init_kernel<<<(vthreads + TB - 1) / TB, TB>>>(h, slice);
        scatter_kernel<<<((size_t)N_EDGES * 32 + TB - 1) / TB, TB>>>(h, slice);
        relu_slice_kernel<<<(vthreads + TB - 1) / TB, TB>>>(slice);
    }

    // final: out = cat @ W_out^T + b_out   (K=512, NC=64)
    {
        dim3 grid((M + 127) / 128, 1);
        sgemm_kernel<128, 64, 8, 8, 8, false><<<grid, 128>>>(cat, CATW, W_out, b_out, out, OUT_CH, M, CATW);
    }
}

// round 2
// speedup vs baseline: 1.2011x; 1.2011x over previous
#include <cuda_runtime.h>
#include <math.h>
#include <stdint.h>

#define N_NODES 50000
#define N_EDGES 800000
#define HID     128
#define OUT_CH  64
#define N_LAYERS 4
#define CATW    (HID * N_LAYERS)   // 512

// ---------------- device scratch (no runtime allocation allowed) ----------------
__device__ float g_x0[(size_t)N_NODES * HID];      // input projection output
__device__ float g_h[(size_t)N_NODES * HID];       // per-layer GEMM output
__device__ float g_cat[(size_t)N_NODES * CATW];    // concatenated layer outputs (post-ReLU)
__device__ int    g_degi[N_NODES];                 // in-degree + 1 (self loop)
__device__ int    g_src[N_EDGES];
__device__ int    g_dst[N_EDGES];
__device__ int    g_off[N_NODES + 1];              // CSR row offsets (by dst)
__device__ int    g_cur[N_NODES];                  // fill cursors
__device__ float2 g_adj[N_EDGES];                  // packed (src_as_float_bits, norm)
__device__ int    g_is64;

// ---------------- edge dtype detection (int64 vs int32) ----------------
__global__ void detect_kernel(const void* ei) {
    const long long* p = (const long long*)ei;
    int bad = 0;
    for (int i = threadIdx.x; i < 1024; i += blockDim.x) {
        long long v = p[i];
        if (v < 0 || v >= (long long)N_NODES) bad = 1;
    }
    bad = __syncthreads_or(bad);
    if (threadIdx.x == 0) g_is64 = bad ? 0 : 1;
}

__global__ void deg_init_kernel() {
    int v = blockIdx.x * blockDim.x + threadIdx.x;
    if (v < N_NODES) g_degi[v] = 1;   // self loop
}

// fused: convert edge index to int32 + count in-degrees
__global__ void convert_count_kernel(const void* ei) {
    int e = blockIdx.x * blockDim.x + threadIdx.x;
    if (e >= N_EDGES) return;
    int s, d;
    if (g_is64) {
        const long long* p = (const long long*)ei;
        s = (int)p[e];
        d = (int)p[N_EDGES + e];
    } else {
        const int* p = (const int*)ei;
        s = p[e];
        d = p[N_EDGES + e];
    }
    g_src[e] = s;
    g_dst[e] = d;
    atomicAdd(&g_degi[d], 1);
}

// single-block exclusive scan of CSR row lengths (in-degree = degi-1); zeroes cursors
__global__ void scan_kernel() {
    const int T = 1024;
    const int CH = (N_NODES + T - 1) / T;  // 49
    __shared__ int s_part[T];
    int t = threadIdx.x;
    int base = t * CH;
    int sum = 0;
    for (int i = 0; i < CH; i++) {
        int v = base + i;
        if (v < N_NODES) sum += g_degi[v] - 1;
    }
    s_part[t] = sum;
    __syncthreads();
    for (int off = 1; off < T; off <<= 1) {
        int add = (t >= off) ? s_part[t - off] : 0;
        __syncthreads();
        s_part[t] += add;
        __syncthreads();
    }
    int run = (t == 0) ? 0 : s_part[t - 1];
    for (int i = 0; i < CH; i++) {
        int v = base + i;
        if (v < N_NODES) {
            g_off[v] = run;
            g_cur[v] = 0;
            run += g_degi[v] - 1;
        }
    }
    if (t == T - 1) g_off[N_NODES] = run;
}

// place edges into CSR (by dst) with precomputed per-edge norm
__global__ void fill_kernel() {
    int e = blockIdx.x * blockDim.x + threadIdx.x;
    if (e >= N_EDGES) return;
    int s = g_src[e], d = g_dst[e];
    int pos = g_off[d] + atomicAdd(&g_cur[d], 1);
    float nm = rsqrtf((float)g_degi[s] * (float)g_degi[d]);
    g_adj[pos] = make_float2(__int_as_float(s), nm);
}

// ---------------- SGEMM: C[M,NC] = A[M,K] @ W[NC,K]^T + bias, optional relu ----------------
template <int BM, int BN, int BK, int TM, int TN, bool RELU>
__global__ void sgemm_kernel(const float* __restrict__ A, int lda,
                             const float* __restrict__ W,
                             const float* __restrict__ bias,
                             float* __restrict__ C, int ldc,
                             int M, int K) {
    constexpr int NT = (BM / TM) * (BN / TN);
    const int m0 = blockIdx.x * BM;
    const int n0 = blockIdx.y * BN;

    __shared__ __align__(16) float As[BK * BM];
    __shared__ __align__(16) float Bs[BK * BN];

    float acc[TM][TN];
#pragma unroll
    for (int i = 0; i < TM; i++)
#pragma unroll
        for (int j = 0; j < TN; j++) acc[i][j] = 0.0f;

    const int tid  = threadIdx.x;
    const int tRow = tid / (BN / TN);
    const int tCol = tid % (BN / TN);

    for (int k0 = 0; k0 < K; k0 += BK) {
#pragma unroll
        for (int idx = tid * 4; idx < BM * BK; idx += NT * 4) {
            int row = idx / BK, col = idx % BK;
            float4 v = make_float4(0.f, 0.f, 0.f, 0.f);
            if (m0 + row < M)
                v = *(const float4*)(A + (size_t)(m0 + row) * lda + k0 + col);
            As[(col + 0) * BM + row] = v.x;
            As[(col + 1) * BM + row] = v.y;
            As[(col + 2) * BM + row] = v.z;
            As[(col + 3) * BM + row] = v.w;
        }
#pragma unroll
        for (int idx = tid * 4; idx < BN * BK; idx += NT * 4) {
            int row = idx / BK, col = idx % BK;
            float4 v = *(const float4*)(W + (size_t)(n0 + row) * K + k0 + col);
            Bs[(col + 0) * BN + row] = v.x;
            Bs[(col + 1) * BN + row] = v.y;
            Bs[(col + 2) * BN + row] = v.z;
            Bs[(col + 3) * BN + row] = v.w;
        }
        __syncthreads();

#pragma unroll
        for (int k = 0; k < BK; k++) {
            float4 a0 = *(const float4*)&As[k * BM + tRow * TM];
            float4 a1 = *(const float4*)&As[k * BM + tRow * TM + 4];
            float4 b0 = *(const float4*)&Bs[k * BN + tCol * TN];
            float4 b1 = *(const float4*)&Bs[k * BN + tCol * TN + 4];
            float rm[TM] = {a0.x, a0.y, a0.z, a0.w, a1.x, a1.y, a1.z, a1.w};
            float rn[TN] = {b0.x, b0.y, b0.z, b0.w, b1.x, b1.y, b1.z, b1.w};
#pragma unroll
            for (int i = 0; i < TM; i++)
#pragma unroll
                for (int j = 0; j < TN; j++) acc[i][j] += rm[i] * rn[j];
        }
        __syncthreads();
    }

#pragma unroll
    for (int i = 0; i < TM; i++) {
        int m = m0 + tRow * TM + i;
        if (m >= M) break;
#pragma unroll
        for (int j = 0; j < TN; j += 4) {
            int n = n0 + tCol * TN + j;
            float4 r;
            r.x = acc[i][j + 0] + bias[n + 0];
            r.y = acc[i][j + 1] + bias[n + 1];
            r.z = acc[i][j + 2] + bias[n + 2];
            r.w = acc[i][j + 3] + bias[n + 3];
            if (RELU) {
                r.x = fmaxf(r.x, 0.f);
                r.y = fmaxf(r.y, 0.f);
                r.z = fmaxf(r.z, 0.f);
                r.w = fmaxf(r.w, 0.f);
            }
            *(float4*)(C + (size_t)m * ldc + n) = r;
        }
    }
}

// ---------------- fused aggregation: gather + self-loop + ReLU ----------------
// one warp per node; each lane owns one float4 feature chunk (32 lanes * 4 = 128)
__global__ void gather_kernel(const float* __restrict__ h, float* __restrict__ cat_slice) {
    int w = (blockIdx.x * blockDim.x + threadIdx.x) >> 5;
    int lane = threadIdx.x & 31;
    if (w >= N_NODES) return;

    int beg = g_off[w];
    int end = g_off[w + 1];
    float dinv = 1.0f / (float)(end - beg + 1);

    // self-loop contribution: h[w] / deg[w]
    float4 acc = ((const float4*)(h + (size_t)w * HID))[lane];
    acc.x *= dinv; acc.y *= dinv; acc.z *= dinv; acc.w *= dinv;

    int i = beg;
    for (; i + 4 <= end; i += 4) {
        float2 p0 = g_adj[i + 0];
        float2 p1 = g_adj[i + 1];
        float2 p2 = g_adj[i + 2];
        float2 p3 = g_adj[i + 3];
        float4 v0 = ((const float4*)(h + (size_t)__float_as_int(p0.x) * HID))[lane];
        float4 v1 = ((const float4*)(h + (size_t)__float_as_int(p1.x) * HID))[lane];
        float4 v2 = ((const float4*)(h + (size_t)__float_as_int(p2.x) * HID))[lane];
        float4 v3 = ((const float4*)(h + (size_t)__float_as_int(p3.x) * HID))[lane];
        acc.x += v0.x * p0.y; acc.y += v0.y * p0.y; acc.z += v0.z * p0.y; acc.w += v0.w * p0.y;
        acc.x += v1.x * p1.y; acc.y += v1.y * p1.y; acc.z += v1.z * p1.y; acc.w += v1.w * p1.y;
        acc.x += v2.x * p2.y; acc.y += v2.y * p2.y; acc.z += v2.z * p2.y; acc.w += v2.w * p2.y;
        acc.x += v3.x * p3.y; acc.y += v3.y * p3.y; acc.z += v3.z * p3.y; acc.w += v3.w * p3.y;
    }
    for (; i < end; i++) {
        float2 p = g_adj[i];
        float4 v = ((const float4*)(h + (size_t)__float_as_int(p.x) * HID))[lane];
        acc.x += v.x * p.y; acc.y += v.y * p.y; acc.z += v.z * p.y; acc.w += v.w * p.y;
    }

    // ReLU fused at the single write point
    acc.x = fmaxf(acc.x, 0.f);
    acc.y = fmaxf(acc.y, 0.f);
    acc.z = fmaxf(acc.z, 0.f);
    acc.w = fmaxf(acc.w, 0.f);
    ((float4*)(cat_slice + (size_t)w * CATW))[lane] = acc;
}

// ---------------- launch ----------------
extern "C" void kernel_launch(void* const* d_in, const int* in_sizes, int n_in,
                              void* d_out, int out_size) {
    const float* x     = (const float*)d_in[0];
    const void*  ei    = d_in[1];
    const float* W_in  = (const float*)d_in[2];
    const float* b_in  = (const float*)d_in[3];
    const float* Wc    = (const float*)d_in[4];
    const float* bc    = (const float*)d_in[5];
    const float* W_out = (const float*)d_in[6];
    const float* b_out = (const float*)d_in[7];
    float* out = (float*)d_out;

    float *x0, *h, *cat;
    cudaGetSymbolAddress((void**)&x0, g_x0);
    cudaGetSymbolAddress((void**)&h, g_h);
    cudaGetSymbolAddress((void**)&cat, g_cat);

    const int TB = 256;
    const int M = N_NODES;

    // ---- CSR preprocessing (runs inside the graph every replay) ----
    detect_kernel<<<1, 256>>>(ei);
    deg_init_kernel<<<(N_NODES + TB - 1) / TB, TB>>>();
    convert_count_kernel<<<(N_EDGES + TB - 1) / TB, TB>>>(ei);
    scan_kernel<<<1, 1024>>>();
    fill_kernel<<<(N_EDGES + TB - 1) / TB, TB>>>();

    // ---- input projection + relu: x0 = relu(x @ W_in^T + b_in) ----
    {
        dim3 grid((M + 127) / 128, 1);
        sgemm_kernel<128, 128, 8, 8, 8, true><<<grid, 256>>>(x, HID, W_in, b_in, x0, HID, M, HID);
    }

    // ---- 4 conv layers: GEMM then fused gather/self-loop/ReLU ----
    const int gwarps_threads = N_NODES * 32;
    for (int L = 0; L < N_LAYERS; L++) {
        const float* A = (L == 0) ? x0 : (cat + (size_t)(L - 1) * HID);
        int lda = (L == 0) ? HID : CATW;
        dim3 grid((M + 127) / 128, 1);
        sgemm_kernel<128, 128, 8, 8, 8, false><<<grid, 256>>>(
            A, lda, Wc + (size_t)L * HID * HID, bc + (size_t)L * HID, h, HID, M, HID);

        gather_kernel<<<(gwarps_threads + TB - 1) / TB, TB>>>(h, cat + (size_t)L * HID);
    }

    // ---- final: out = cat @ W_out^T + b_out   (K=512, NC=64) ----
    {
        dim3 grid((M + 127) / 128, 1);
        sgemm_kernel<128, 64, 8, 8, 8, false><<<grid, 128>>>(cat, CATW, W_out, b_out, out, OUT_CH, M, CATW);
    }
}

// round 4
// speedup vs baseline: 2.5105x; 2.0902x over previous
#include <cuda_runtime.h>
#include <cuda_bf16.h>
#include <math.h>
#include <stdint.h>

#define N_NODES 50000
#define N_EDGES 800000
#define HID     128
#define OUT_CH  64
#define N_LAYERS 4
#define CATW    (HID * N_LAYERS)   // 512

// ================= device scratch =================
__device__ float  g_x0[(size_t)N_NODES * HID];
__device__ float  g_h[(size_t)N_NODES * HID];
__device__ float  g_cat[(size_t)N_NODES * CATW];
__device__ int    g_degi[N_NODES];
__device__ int    g_src[N_EDGES];
__device__ int    g_dst[N_EDGES];
__device__ int    g_off[N_NODES + 1];
__device__ int    g_cur[N_NODES];
__device__ float2 g_adj[N_EDGES];
__device__ int    g_is64;

#define SCAN_B 256
#define NBLK ((N_NODES + SCAN_B - 1) / SCAN_B)   // 196
__device__ int g_bsum[NBLK];

// ================= preprocessing =================
__global__ void detect_kernel(const void* ei) {
    const long long* p = (const long long*)ei;
    int bad = 0;
    for (int i = threadIdx.x; i < 1024; i += blockDim.x) {
        long long v = p[i];
        if (v < 0 || v >= (long long)N_NODES) bad = 1;
    }
    bad = __syncthreads_or(bad);
    if (threadIdx.x == 0) g_is64 = bad ? 0 : 1;
}
__global__ void deg_init_kernel() {
    int v = blockIdx.x * blockDim.x + threadIdx.x;
    if (v < N_NODES) g_degi[v] = 1;
}
__global__ void convert_count_kernel(const void* ei) {
    int e = blockIdx.x * blockDim.x + threadIdx.x;
    if (e >= N_EDGES) return;
    int s, d;
    if (g_is64) {
        const long long* p = (const long long*)ei;
        s = (int)p[e];
        d = (int)p[N_EDGES + e];
    } else {
        const int* p = (const int*)ei;
        s = p[e];
        d = p[N_EDGES + e];
    }
    g_src[e] = s;
    g_dst[e] = d;
    atomicAdd(&g_degi[d], 1);
}
__global__ void scan1_kernel() {
    __shared__ int s[SCAN_B];
    int t = threadIdx.x;
    int v = blockIdx.x * SCAN_B + t;
    s[t] = (v < N_NODES) ? (g_degi[v] - 1) : 0;
    __syncthreads();
    for (int off = SCAN_B / 2; off > 0; off >>= 1) {
        if (t < off) s[t] += s[t + off];
        __syncthreads();
    }
    if (t == 0) g_bsum[blockIdx.x] = s[0];
}
__global__ void scan2_kernel() {
    __shared__ int s[SCAN_B];
    int t = threadIdx.x;
    int v = (t < NBLK) ? g_bsum[t] : 0;
    s[t] = v;
    __syncthreads();
    for (int off = 1; off < SCAN_B; off <<= 1) {
        int a = (t >= off) ? s[t - off] : 0;
        __syncthreads();
        s[t] += a;
        __syncthreads();
    }
    if (t < NBLK) g_bsum[t] = s[t] - v;
    if (t == NBLK - 1) g_off[N_NODES] = s[t];
}
__global__ void scan3_kernel() {
    __shared__ int s[SCAN_B];
    int t = threadIdx.x;
    int v = blockIdx.x * SCAN_B + t;
    int d = (v < N_NODES) ? (g_degi[v] - 1) : 0;
    s[t] = d;
    __syncthreads();
    for (int off = 1; off < SCAN_B; off <<= 1) {
        int a = (t >= off) ? s[t - off] : 0;
        __syncthreads();
        s[t] += a;
        __syncthreads();
    }
    if (v < N_NODES) {
        g_off[v] = g_bsum[blockIdx.x] + s[t] - d;
        g_cur[v] = 0;
    }
}
__global__ void fill_kernel() {
    int e = blockIdx.x * blockDim.x + threadIdx.x;
    if (e >= N_EDGES) return;
    int s = g_src[e], d = g_dst[e];
    int pos = g_off[d] + atomicAdd(&g_cur[d], 1);
    float nm = rsqrtf((float)g_degi[s] * (float)g_degi[d]);
    g_adj[pos] = make_float2(__int_as_float(s), nm);
}

// ================= bf16x2-split tensor-core GEMM (mma.sync, sm_80 baseline PTX) =================
// C[M, NN] = A[M, K] @ W[NN, K]^T + bias, optional ReLU.
// fp32 split: x = hi_bf16 + lo_bf16; D = Ahi*Bhi + Ahi*Blo + Alo*Bhi (err ~2^-18)
// CTA: 128 x NN tile, 8 warps (4m x 2n), warp tile 32 x NN/2. K chunked by 32.

__device__ __forceinline__ uint32_t pack2(float lo_elem, float hi_elem) {
    __nv_bfloat162 t = __floats2bfloat162_rn(lo_elem, hi_elem);  // .x = first = low bits
    return *(uint32_t*)&t;
}
__device__ __forceinline__ void hilo(float x, float& h, float& l) {
    float hf = __bfloat162float(__float2bfloat16_rn(x));
    h = hf;
    l = x - hf;
}
__device__ __forceinline__ void mma16816(float* c, const uint32_t* a, const uint32_t* b) {
    asm volatile(
        "mma.sync.aligned.m16n8k16.row.col.f32.bf16.bf16.f32 "
        "{%0,%1,%2,%3}, {%4,%5,%6,%7}, {%8,%9}, {%0,%1,%2,%3};"
        : "+f"(c[0]), "+f"(c[1]), "+f"(c[2]), "+f"(c[3])
        : "r"(a[0]), "r"(a[1]), "r"(a[2]), "r"(a[3]), "r"(b[0]), "r"(b[1]));
}

#define PADU 20   // u32 stride per row (conflict-free fragment loads)

template <int NN, bool RELU>
__global__ void __launch_bounds__(256) mma_gemm_kernel(
    const float* __restrict__ A, int lda,
    const float* __restrict__ W,
    const float* __restrict__ bias,
    float* __restrict__ C, int ldc,
    int M, int K)
{
    __shared__ uint32_t sAh[128 * PADU];
    __shared__ uint32_t sAl[128 * PADU];
    __shared__ uint32_t sBh[NN * PADU];
    __shared__ uint32_t sBl[NN * PADU];

    const int tid = threadIdx.x;
    const int wid = tid >> 5;
    const int lane = tid & 31;
    const int gr = lane >> 2;      // 0..7
    const int gc = lane & 3;       // 0..3
    const int warp_m = wid >> 1;   // 0..3
    const int warp_n = wid & 1;    // 0..1
    const int m0 = blockIdx.x * 128;
    constexpr int NT = NN / 16;    // n-tiles per warp (8 or 4)

    float acc[2][NT][4];
#pragma unroll
    for (int mt = 0; mt < 2; mt++)
#pragma unroll
        for (int nt = 0; nt < NT; nt++)
#pragma unroll
            for (int j = 0; j < 4; j++) acc[mt][nt][j] = 0.0f;

    const int chunks = K >> 5;

    for (int c = 0; c < chunks; c++) {
        const int k0 = c << 5;

        // stage A: 128 rows x 32 k, hi/lo bf16x2
#pragma unroll
        for (int it = 0; it < 4; it++) {
            int idx = tid + it * 256;        // 0..1023
            int row = idx >> 3, q = idx & 7; // q: float4 index along k
            float4 v = make_float4(0.f, 0.f, 0.f, 0.f);
            if (m0 + row < M)
                v = *(const float4*)(A + (size_t)(m0 + row) * lda + k0 + q * 4);
            float h0, h1, h2, h3, l0, l1, l2, l3;
            hilo(v.x, h0, l0); hilo(v.y, h1, l1); hilo(v.z, h2, l2); hilo(v.w, h3, l3);
            int base = row * PADU + 2 * q;
            sAh[base + 0] = pack2(h0, h1);
            sAh[base + 1] = pack2(h2, h3);
            sAl[base + 0] = pack2(l0, l1);
            sAl[base + 1] = pack2(l2, l3);
        }
        // stage B: NN rows x 32 k
#pragma unroll
        for (int it = 0; it < NN / 32; it++) {
            int idx = tid + it * 256;
            int row = idx >> 3, q = idx & 7;
            float4 v = *(const float4*)(W + (size_t)row * K + k0 + q * 4);
            float h0, h1, h2, h3, l0, l1, l2, l3;
            hilo(v.x, h0, l0); hilo(v.y, h1, l1); hilo(v.z, h2, l2); hilo(v.w, h3, l3);
            int base = row * PADU + 2 * q;
            sBh[base + 0] = pack2(h0, h1);
            sBh[base + 1] = pack2(h2, h3);
            sBl[base + 0] = pack2(l0, l1);
            sBl[base + 1] = pack2(l2, l3);
        }
        __syncthreads();

#pragma unroll
        for (int s = 0; s < 2; s++) {        // two k16 steps per 32-chunk
            const int kc = s * 8 + gc;       // u32 column within chunk
            uint32_t ah[2][4], al[2][4];
#pragma unroll
            for (int mt = 0; mt < 2; mt++) {
                int r = warp_m * 32 + mt * 16 + gr;
                ah[mt][0] = sAh[r * PADU + kc];
                ah[mt][1] = sAh[(r + 8) * PADU + kc];
                ah[mt][2] = sAh[r * PADU + kc + 4];
                ah[mt][3] = sAh[(r + 8) * PADU + kc + 4];
                al[mt][0] = sAl[r * PADU + kc];
                al[mt][1] = sAl[(r + 8) * PADU + kc];
                al[mt][2] = sAl[r * PADU + kc + 4];
                al[mt][3] = sAl[(r + 8) * PADU + kc + 4];
            }
#pragma unroll
            for (int nt = 0; nt < NT; nt++) {
                int n = warp_n * (NN / 2) + nt * 8 + gr;
                uint32_t bh[2], bl[2];
                bh[0] = sBh[n * PADU + kc];
                bh[1] = sBh[n * PADU + kc + 4];
                bl[0] = sBl[n * PADU + kc];
                bl[1] = sBl[n * PADU + kc + 4];
#pragma unroll
                for (int mt = 0; mt < 2; mt++) {
                    mma16816(acc[mt][nt], ah[mt], bh);
                    mma16816(acc[mt][nt], ah[mt], bl);
                    mma16816(acc[mt][nt], al[mt], bh);
                }
            }
        }
        __syncthreads();
    }

    // epilogue
#pragma unroll
    for (int mt = 0; mt < 2; mt++) {
#pragma unroll
        for (int nt = 0; nt < NT; nt++) {
            int col = warp_n * (NN / 2) + nt * 8 + 2 * gc;
            float b0 = __ldg(bias + col);
            float b1 = __ldg(bias + col + 1);
            int r0 = m0 + warp_m * 32 + mt * 16 + gr;
            float2 o;
            if (r0 < M) {
                o.x = acc[mt][nt][0] + b0;
                o.y = acc[mt][nt][1] + b1;
                if (RELU) { o.x = fmaxf(o.x, 0.f); o.y = fmaxf(o.y, 0.f); }
                *(float2*)(C + (size_t)r0 * ldc + col) = o;
            }
            int r1 = r0 + 8;
            if (r1 < M) {
                o.x = acc[mt][nt][2] + b0;
                o.y = acc[mt][nt][3] + b1;
                if (RELU) { o.x = fmaxf(o.x, 0.f); o.y = fmaxf(o.y, 0.f); }
                *(float2*)(C + (size_t)r1 * ldc + col) = o;
            }
        }
    }
}

// ================= fused aggregation: gather + self-loop + ReLU =================
__global__ void gather_kernel(const float* __restrict__ h, float* __restrict__ cat_slice) {
    int w = (blockIdx.x * blockDim.x + threadIdx.x) >> 5;
    int lane = threadIdx.x & 31;
    if (w >= N_NODES) return;

    int beg = g_off[w];
    int end = g_off[w + 1];
    float dinv = 1.0f / (float)(end - beg + 1);

    float4 acc = ((const float4*)(h + (size_t)w * HID))[lane];
    acc.x *= dinv; acc.y *= dinv; acc.z *= dinv; acc.w *= dinv;

    int i = beg;
    for (; i + 4 <= end; i += 4) {
        float2 p0 = g_adj[i + 0];
        float2 p1 = g_adj[i + 1];
        float2 p2 = g_adj[i + 2];
        float2 p3 = g_adj[i + 3];
        float4 v0 = ((const float4*)(h + (size_t)__float_as_int(p0.x) * HID))[lane];
        float4 v1 = ((const float4*)(h + (size_t)__float_as_int(p1.x) * HID))[lane];
        float4 v2 = ((const float4*)(h + (size_t)__float_as_int(p2.x) * HID))[lane];
        float4 v3 = ((const float4*)(h + (size_t)__float_as_int(p3.x) * HID))[lane];
        acc.x += v0.x * p0.y; acc.y += v0.y * p0.y; acc.z += v0.z * p0.y; acc.w += v0.w * p0.y;
        acc.x += v1.x * p1.y; acc.y += v1.y * p1.y; acc.z += v1.z * p1.y; acc.w += v1.w * p1.y;
        acc.x += v2.x * p2.y; acc.y += v2.y * p2.y; acc.z += v2.z * p2.y; acc.w += v2.w * p2.y;
        acc.x += v3.x * p3.y; acc.y += v3.y * p3.y; acc.z += v3.z * p3.y; acc.w += v3.w * p3.y;
    }
    for (; i < end; i++) {
        float2 p = g_adj[i];
        float4 v = ((const float4*)(h + (size_t)__float_as_int(p.x) * HID))[lane];
        acc.x += v.x * p.y; acc.y += v.y * p.y; acc.z += v.z * p.y; acc.w += v.w * p.y;
    }

    acc.x = fmaxf(acc.x, 0.f);
    acc.y = fmaxf(acc.y, 0.f);
    acc.z = fmaxf(acc.z, 0.f);
    acc.w = fmaxf(acc.w, 0.f);
    ((float4*)(cat_slice + (size_t)w * CATW))[lane] = acc;
}

// ================= launch =================
extern "C" void kernel_launch(void* const* d_in, const int* in_sizes, int n_in,
                              void* d_out, int out_size) {
    const float* x     = (const float*)d_in[0];
    const void*  ei    = d_in[1];
    const float* W_in  = (const float*)d_in[2];
    const float* b_in  = (const float*)d_in[3];
    const float* Wc    = (const float*)d_in[4];
    const float* bc    = (const float*)d_in[5];
    const float* W_out = (const float*)d_in[6];
    const float* b_out = (const float*)d_in[7];
    float* out = (float*)d_out;

    float *x0, *h, *cat;
    cudaGetSymbolAddress((void**)&x0, g_x0);
    cudaGetSymbolAddress((void**)&h, g_h);
    cudaGetSymbolAddress((void**)&cat, g_cat);

    const int TB = 256;
    const int M = N_NODES;
    const int GB = (M + 127) / 128;   // 391

    // ---- CSR preprocessing ----
    detect_kernel<<<1, 256>>>(ei);
    deg_init_kernel<<<(N_NODES + TB - 1) / TB, TB>>>();
    convert_count_kernel<<<(N_EDGES + TB - 1) / TB, TB>>>(ei);
    scan1_kernel<<<NBLK, SCAN_B>>>();
    scan2_kernel<<<1, SCAN_B>>>();
    scan3_kernel<<<NBLK, SCAN_B>>>();
    fill_kernel<<<(N_EDGES + TB - 1) / TB, TB>>>();

    // ---- input projection + relu ----
    mma_gemm_kernel<128, true><<<GB, 256>>>(x, HID, W_in, b_in, x0, HID, M, HID);

    // ---- conv layers ----
    const int gthreads = N_NODES * 32;
    for (int L = 0; L < N_LAYERS; L++) {
        const float* A = (L == 0) ? x0 : (cat + (size_t)(L - 1) * HID);
        int lda = (L == 0) ? HID : CATW;
        mma_gemm_kernel<128, false><<<GB, 256>>>(
            A, lda, Wc + (size_t)L * HID * HID, bc + (size_t)L * HID, h, HID, M, HID);
        gather_kernel<<<(gthreads + TB - 1) / TB, TB>>>(h, cat + (size_t)L * HID);
    }

    // ---- final projection: K=512, NN=64 ----
    mma_gemm_kernel<64, false><<<GB, 256>>>(cat, CATW, W_out, b_out, out, OUT_CH, M, CATW);
}

// round 5
// speedup vs baseline: 2.5679x; 1.0229x over previous
#include <cuda_runtime.h>
#include <cuda_bf16.h>
#include <math.h>
#include <stdint.h>

#define N_NODES 50000
#define N_EDGES 800000
#define HID     128
#define OUT_CH  64
#define N_LAYERS 4
#define CATW    (HID * N_LAYERS)   // 512
#define CATU    (CATW / 2)         // 256 u32 per row

// weight regions in split-u32 space
#define WU_IN   0                          // 128*64
#define WU_C    8192                       // 4 * 128*64
#define WU_OUT  (WU_C + 4 * 8192)          // 64*256
#define WU_TOT  (WU_OUT + 16384)           // 57344

// ================= device scratch =================
__device__ __align__(16) uint32_t g_x0h[(size_t)N_NODES * HID / 2];
__device__ __align__(16) uint32_t g_x0l[(size_t)N_NODES * HID / 2];
__device__ float  g_h[(size_t)N_NODES * HID];
__device__ __align__(16) uint32_t g_cath[(size_t)N_NODES * CATU];
__device__ __align__(16) uint32_t g_catl[(size_t)N_NODES * CATU];
__device__ __align__(16) uint32_t g_wh[WU_TOT];
__device__ __align__(16) uint32_t g_wl[WU_TOT];
__device__ int    g_degi[N_NODES];
__device__ int    g_src[N_EDGES];
__device__ int    g_dst[N_EDGES];
__device__ int    g_off[N_NODES + 1];
__device__ int    g_cur[N_NODES];
__device__ float2 g_adj[N_EDGES];
__device__ int    g_is64;

#define SCAN_B 256
#define NBLK ((N_NODES + SCAN_B - 1) / SCAN_B)   // 196
__device__ int g_bsum[NBLK];

// ================= helpers =================
__device__ __forceinline__ uint32_t pack2(float lo_elem, float hi_elem) {
    __nv_bfloat162 t = __floats2bfloat162_rn(lo_elem, hi_elem);  // .x -> low 16 bits
    return *(uint32_t*)&t;
}
__device__ __forceinline__ void hilo(float x, float& h, float& l) {
    float hf = __bfloat162float(__float2bfloat16_rn(x));
    h = hf;
    l = x - hf;
}
__device__ __forceinline__ void mma16816(float* c, const uint32_t* a, const uint32_t* b) {
    asm volatile(
        "mma.sync.aligned.m16n8k16.row.col.f32.bf16.bf16.f32 "
        "{%0,%1,%2,%3}, {%4,%5,%6,%7}, {%8,%9}, {%0,%1,%2,%3};"
        : "+f"(c[0]), "+f"(c[1]), "+f"(c[2]), "+f"(c[3])
        : "r"(a[0]), "r"(a[1]), "r"(a[2]), "r"(a[3]), "r"(b[0]), "r"(b[1]));
}

// ================= preprocessing =================
__global__ void detect_kernel(const void* ei) {
    const long long* p = (const long long*)ei;
    int bad = 0;
    for (int i = threadIdx.x; i < 1024; i += blockDim.x) {
        long long v = p[i];
        if (v < 0 || v >= (long long)N_NODES) bad = 1;
    }
    bad = __syncthreads_or(bad);
    if (threadIdx.x == 0) g_is64 = bad ? 0 : 1;
}
__global__ void deg_init_kernel() {
    int v = blockIdx.x * blockDim.x + threadIdx.x;
    if (v < N_NODES) g_degi[v] = 1;
}
__global__ void convert_count_kernel(const void* ei) {
    int e = blockIdx.x * blockDim.x + threadIdx.x;
    if (e >= N_EDGES) return;
    int s, d;
    if (g_is64) {
        const long long* p = (const long long*)ei;
        s = (int)p[e];
        d = (int)p[N_EDGES + e];
    } else {
        const int* p = (const int*)ei;
        s = p[e];
        d = p[N_EDGES + e];
    }
    g_src[e] = s;
    g_dst[e] = d;
    atomicAdd(&g_degi[d], 1);
}
__global__ void scan1_kernel() {
    __shared__ int s[SCAN_B];
    int t = threadIdx.x;
    int v = blockIdx.x * SCAN_B + t;
    s[t] = (v < N_NODES) ? (g_degi[v] - 1) : 0;
    __syncthreads();
    for (int off = SCAN_B / 2; off > 0; off >>= 1) {
        if (t < off) s[t] += s[t + off];
        __syncthreads();
    }
    if (t == 0) g_bsum[blockIdx.x] = s[0];
}
__global__ void scan2_kernel() {
    __shared__ int s[SCAN_B];
    int t = threadIdx.x;
    int v = (t < NBLK) ? g_bsum[t] : 0;
    s[t] = v;
    __syncthreads();
    for (int off = 1; off < SCAN_B; off <<= 1) {
        int a = (t >= off) ? s[t - off] : 0;
        __syncthreads();
        s[t] += a;
        __syncthreads();
    }
    if (t < NBLK) g_bsum[t] = s[t] - v;
    if (t == NBLK - 1) g_off[N_NODES] = s[t];
}
__global__ void scan3_kernel() {
    __shared__ int s[SCAN_B];
    int t = threadIdx.x;
    int v = blockIdx.x * SCAN_B + t;
    int d = (v < N_NODES) ? (g_degi[v] - 1) : 0;
    s[t] = d;
    __syncthreads();
    for (int off = 1; off < SCAN_B; off <<= 1) {
        int a = (t >= off) ? s[t - off] : 0;
        __syncthreads();
        s[t] += a;
        __syncthreads();
    }
    if (v < N_NODES) {
        g_off[v] = g_bsum[blockIdx.x] + s[t] - d;
        g_cur[v] = 0;
    }
}
__global__ void fill_kernel() {
    int e = blockIdx.x * blockDim.x + threadIdx.x;
    if (e >= N_EDGES) return;
    int s = g_src[e], d = g_dst[e];
    int pos = g_off[d] + atomicAdd(&g_cur[d], 1);
    float nm = rsqrtf((float)g_degi[s] * (float)g_degi[d]);
    g_adj[pos] = make_float2(__int_as_float(s), nm);
}

// ================= weight split (once per launch) =================
__global__ void split_w_kernel(const float* __restrict__ W_in,
                               const float* __restrict__ Wc,
                               const float* __restrict__ W_out) {
    int t = blockIdx.x * blockDim.x + threadIdx.x;
    if (t >= WU_TOT) return;
    const float* src;
    int rt;
    if (t < WU_C) { src = W_in; rt = t; }
    else if (t < WU_OUT) { src = Wc; rt = t - WU_C; }
    else { src = W_out; rt = t - WU_OUT; }
    float a = src[2 * rt], b = src[2 * rt + 1];
    float ha, la, hb, lb;
    hilo(a, ha, la);
    hilo(b, hb, lb);
    g_wh[t] = pack2(ha, hb);
    g_wl[t] = pack2(la, lb);
}

// ================= bf16x2-split tensor-core GEMM (pre-split A and W) =================
// C[M, NN] = A[M, K] @ W[NN, K]^T + bias.
// EPI_SPLIT=false: write fp32 C (no relu). EPI_SPLIT=true: relu + write hi/lo u32.
#define PADU 20

template <int NN, bool EPI_SPLIT>
__global__ void __launch_bounds__(256) mma_gemm_split(
    const uint32_t* __restrict__ Ah, const uint32_t* __restrict__ Al, int lda_u,
    const uint32_t* __restrict__ Bh, const uint32_t* __restrict__ Bl,
    const float* __restrict__ bias,
    float* __restrict__ Cf, int ldc,
    uint32_t* __restrict__ Chi, uint32_t* __restrict__ Clo, int ldc_u,
    int M, int K)
{
    __shared__ uint32_t sAh[128 * PADU];
    __shared__ uint32_t sAl[128 * PADU];
    __shared__ uint32_t sBh[NN * PADU];
    __shared__ uint32_t sBl[NN * PADU];

    const int tid = threadIdx.x;
    const int wid = tid >> 5;
    const int lane = tid & 31;
    const int gr = lane >> 2;
    const int gc = lane & 3;
    const int warp_m = wid >> 1;
    const int warp_n = wid & 1;
    const int m0 = blockIdx.x * 128;
    constexpr int NT = NN / 16;

    float acc[2][NT][4];
#pragma unroll
    for (int mt = 0; mt < 2; mt++)
#pragma unroll
        for (int nt = 0; nt < NT; nt++)
#pragma unroll
            for (int j = 0; j < 4; j++) acc[mt][nt][j] = 0.0f;

    const int Ku = K >> 1;
    const int chunks = K >> 5;

    for (int c = 0; c < chunks; c++) {
        const int k0u = c << 4;   // 16 u32 per chunk

        // stage A: 128 rows x 16 u32, pure copies
#pragma unroll
        for (int it = 0; it < 2; it++) {
            int idx = tid + it * 256;          // 0..511
            int row = idx >> 2, j = idx & 3;
            uint4 vh = make_uint4(0, 0, 0, 0), vl = make_uint4(0, 0, 0, 0);
            if (m0 + row < M) {
                const uint32_t* pa = Ah + (size_t)(m0 + row) * lda_u + k0u + j * 4;
                const uint32_t* pl = Al + (size_t)(m0 + row) * lda_u + k0u + j * 4;
                vh = *(const uint4*)pa;
                vl = *(const uint4*)pl;
            }
            *(uint4*)&sAh[row * PADU + j * 4] = vh;
            *(uint4*)&sAl[row * PADU + j * 4] = vl;
        }
        // stage B: NN rows x 16 u32
#pragma unroll
        for (int it = 0; it < NN / 64; it++) {
            int idx = tid + it * 256;
            int row = idx >> 2, j = idx & 3;
            uint4 vh = *(const uint4*)(Bh + (size_t)row * Ku + k0u + j * 4);
            uint4 vl = *(const uint4*)(Bl + (size_t)row * Ku + k0u + j * 4);
            *(uint4*)&sBh[row * PADU + j * 4] = vh;
            *(uint4*)&sBl[row * PADU + j * 4] = vl;
        }
        __syncthreads();

#pragma unroll
        for (int s = 0; s < 2; s++) {
            const int kc = s * 8 + gc;
            uint32_t ah[2][4], al[2][4];
#pragma unroll
            for (int mt = 0; mt < 2; mt++) {
                int r = warp_m * 32 + mt * 16 + gr;
                ah[mt][0] = sAh[r * PADU + kc];
                ah[mt][1] = sAh[(r + 8) * PADU + kc];
                ah[mt][2] = sAh[r * PADU + kc + 4];
                ah[mt][3] = sAh[(r + 8) * PADU + kc + 4];
                al[mt][0] = sAl[r * PADU + kc];
                al[mt][1] = sAl[(r + 8) * PADU + kc];
                al[mt][2] = sAl[r * PADU + kc + 4];
                al[mt][3] = sAl[(r + 8) * PADU + kc + 4];
            }
#pragma unroll
            for (int nt = 0; nt < NT; nt++) {
                int n = warp_n * (NN / 2) + nt * 8 + gr;
                uint32_t bh[2], bl[2];
                bh[0] = sBh[n * PADU + kc];
                bh[1] = sBh[n * PADU + kc + 4];
                bl[0] = sBl[n * PADU + kc];
                bl[1] = sBl[n * PADU + kc + 4];
#pragma unroll
                for (int mt = 0; mt < 2; mt++) {
                    mma16816(acc[mt][nt], ah[mt], bh);
                    mma16816(acc[mt][nt], ah[mt], bl);
                    mma16816(acc[mt][nt], al[mt], bh);
                }
            }
        }
        __syncthreads();
    }

    // epilogue
#pragma unroll
    for (int mt = 0; mt < 2; mt++) {
#pragma unroll
        for (int nt = 0; nt < NT; nt++) {
            int col = warp_n * (NN / 2) + nt * 8 + 2 * gc;
            float b0 = __ldg(bias + col);
            float b1 = __ldg(bias + col + 1);
#pragma unroll
            for (int half = 0; half < 2; half++) {
                int r = m0 + warp_m * 32 + mt * 16 + gr + half * 8;
                if (r >= M) continue;
                float ox = acc[mt][nt][2 * half + 0] + b0;
                float oy = acc[mt][nt][2 * half + 1] + b1;
                if (EPI_SPLIT) {
                    ox = fmaxf(ox, 0.f);
                    oy = fmaxf(oy, 0.f);
                    float hx, lx, hy, ly;
                    hilo(ox, hx, lx);
                    hilo(oy, hy, ly);
                    Chi[(size_t)r * ldc_u + col / 2] = pack2(hx, hy);
                    Clo[(size_t)r * ldc_u + col / 2] = pack2(lx, ly);
                } else {
                    float2 o = make_float2(ox, oy);
                    *(float2*)(Cf + (size_t)r * ldc + col) = o;
                }
            }
        }
    }
}

// ================= fused aggregation: gather + self-loop + ReLU + split =================
__global__ void gather_kernel(const float* __restrict__ h,
                              uint32_t* __restrict__ cat_hi,
                              uint32_t* __restrict__ cat_lo) {
    int w = (blockIdx.x * blockDim.x + threadIdx.x) >> 5;
    int lane = threadIdx.x & 31;
    if (w >= N_NODES) return;

    int beg = g_off[w];
    int end = g_off[w + 1];
    float dinv = 1.0f / (float)(end - beg + 1);

    float4 acc = ((const float4*)(h + (size_t)w * HID))[lane];
    acc.x *= dinv; acc.y *= dinv; acc.z *= dinv; acc.w *= dinv;

    int i = beg;
    for (; i + 4 <= end; i += 4) {
        float2 p0 = g_adj[i + 0];
        float2 p1 = g_adj[i + 1];
        float2 p2 = g_adj[i + 2];
        float2 p3 = g_adj[i + 3];
        float4 v0 = ((const float4*)(h + (size_t)__float_as_int(p0.x) * HID))[lane];
        float4 v1 = ((const float4*)(h + (size_t)__float_as_int(p1.x) * HID))[lane];
        float4 v2 = ((const float4*)(h + (size_t)__float_as_int(p2.x) * HID))[lane];
        float4 v3 = ((const float4*)(h + (size_t)__float_as_int(p3.x) * HID))[lane];
        acc.x += v0.x * p0.y; acc.y += v0.y * p0.y; acc.z += v0.z * p0.y; acc.w += v0.w * p0.y;
        acc.x += v1.x * p1.y; acc.y += v1.y * p1.y; acc.z += v1.z * p1.y; acc.w += v1.w * p1.y;
        acc.x += v2.x * p2.y; acc.y += v2.y * p2.y; acc.z += v2.z * p2.y; acc.w += v2.w * p2.y;
        acc.x += v3.x * p3.y; acc.y += v3.y * p3.y; acc.z += v3.z * p3.y; acc.w += v3.w * p3.y;
    }
    for (; i < end; i++) {
        float2 p = g_adj[i];
        float4 v = ((const float4*)(h + (size_t)__float_as_int(p.x) * HID))[lane];
        acc.x += v.x * p.y; acc.y += v.y * p.y; acc.z += v.z * p.y; acc.w += v.w * p.y;
    }

    acc.x = fmaxf(acc.x, 0.f);
    acc.y = fmaxf(acc.y, 0.f);
    acc.z = fmaxf(acc.z, 0.f);
    acc.w = fmaxf(acc.w, 0.f);

    float h0, l0, h1, l1, h2, l2, h3, l3;
    hilo(acc.x, h0, l0);
    hilo(acc.y, h1, l1);
    hilo(acc.z, h2, l2);
    hilo(acc.w, h3, l3);
    uint2 uhi = make_uint2(pack2(h0, h1), pack2(h2, h3));
    uint2 ulo = make_uint2(pack2(l0, l1), pack2(l2, l3));
    *(uint2*)(cat_hi + (size_t)w * CATU + 2 * lane) = uhi;
    *(uint2*)(cat_lo + (size_t)w * CATU + 2 * lane) = ulo;
}

// ================= input-projection GEMM (A fp32 external, converts in staging) =================
__global__ void __launch_bounds__(256) mma_gemm_inproj(
    const float* __restrict__ A,
    const uint32_t* __restrict__ Bh, const uint32_t* __restrict__ Bl,
    const float* __restrict__ bias,
    uint32_t* __restrict__ Chi, uint32_t* __restrict__ Clo,
    int M)
{
    constexpr int NN = 128;
    constexpr int K = 128;
    __shared__ uint32_t sAh[128 * PADU];
    __shared__ uint32_t sAl[128 * PADU];
    __shared__ uint32_t sBh[NN * PADU];
    __shared__ uint32_t sBl[NN * PADU];

    const int tid = threadIdx.x;
    const int wid = tid >> 5;
    const int lane = tid & 31;
    const int gr = lane >> 2;
    const int gc = lane & 3;
    const int warp_m = wid >> 1;
    const int warp_n = wid & 1;
    const int m0 = blockIdx.x * 128;
    constexpr int NT = NN / 16;

    float acc[2][NT][4];
#pragma unroll
    for (int mt = 0; mt < 2; mt++)
#pragma unroll
        for (int nt = 0; nt < NT; nt++)
#pragma unroll
            for (int j = 0; j < 4; j++) acc[mt][nt][j] = 0.0f;

    for (int c = 0; c < 4; c++) {
        const int k0 = c << 5;
        const int k0u = c << 4;
        // stage A with conversion
#pragma unroll
        for (int it = 0; it < 4; it++) {
            int idx = tid + it * 256;
            int row = idx >> 3, q = idx & 7;
            float4 v = make_float4(0.f, 0.f, 0.f, 0.f);
            if (m0 + row < M)
                v = *(const float4*)(A + (size_t)(m0 + row) * K + k0 + q * 4);
            float h0, h1, h2, h3, l0, l1, l2, l3;
            hilo(v.x, h0, l0); hilo(v.y, h1, l1); hilo(v.z, h2, l2); hilo(v.w, h3, l3);
            int base = row * PADU + 2 * q;
            sAh[base + 0] = pack2(h0, h1);
            sAh[base + 1] = pack2(h2, h3);
            sAl[base + 0] = pack2(l0, l1);
            sAl[base + 1] = pack2(l2, l3);
        }
        // stage B from pre-split weights
#pragma unroll
        for (int it = 0; it < 2; it++) {
            int idx = tid + it * 256;
            int row = idx >> 2, j = idx & 3;
            uint4 vh = *(const uint4*)(Bh + (size_t)row * 64 + k0u + j * 4);
            uint4 vl = *(const uint4*)(Bl + (size_t)row * 64 + k0u + j * 4);
            *(uint4*)&sBh[row * PADU + j * 4] = vh;
            *(uint4*)&sBl[row * PADU + j * 4] = vl;
        }
        __syncthreads();

#pragma unroll
        for (int s = 0; s < 2; s++) {
            const int kc = s * 8 + gc;
            uint32_t ah[2][4], al[2][4];
#pragma unroll
            for (int mt = 0; mt < 2; mt++) {
                int r = warp_m * 32 + mt * 16 + gr;
                ah[mt][0] = sAh[r * PADU + kc];
                ah[mt][1] = sAh[(r + 8) * PADU + kc];
                ah[mt][2] = sAh[r * PADU + kc + 4];
                ah[mt][3] = sAh[(r + 8) * PADU + kc + 4];
                al[mt][0] = sAl[r * PADU + kc];
                al[mt][1] = sAl[(r + 8) * PADU + kc];
                al[mt][2] = sAl[r * PADU + kc + 4];
                al[mt][3] = sAl[(r + 8) * PADU + kc + 4];
            }
#pragma unroll
            for (int nt = 0; nt < NT; nt++) {
                int n = warp_n * (NN / 2) + nt * 8 + gr;
                uint32_t bh[2], bl[2];
                bh[0] = sBh[n * PADU + kc];
                bh[1] = sBh[n * PADU + kc + 4];
                bl[0] = sBl[n * PADU + kc];
                bl[1] = sBl[n * PADU + kc + 4];
#pragma unroll
                for (int mt = 0; mt < 2; mt++) {
                    mma16816(acc[mt][nt], ah[mt], bh);
                    mma16816(acc[mt][nt], ah[mt], bl);
                    mma16816(acc[mt][nt], al[mt], bh);
                }
            }
        }
        __syncthreads();
    }

    // epilogue: relu + split store
#pragma unroll
    for (int mt = 0; mt < 2; mt++) {
#pragma unroll
        for (int nt = 0; nt < NT; nt++) {
            int col = warp_n * (NN / 2) + nt * 8 + 2 * gc;
            float b0 = __ldg(bias + col);
            float b1 = __ldg(bias + col + 1);
#pragma unroll
            for (int half = 0; half < 2; half++) {
                int r = m0 + warp_m * 32 + mt * 16 + gr + half * 8;
                if (r >= M) continue;
                float ox = fmaxf(acc[mt][nt][2 * half + 0] + b0, 0.f);
                float oy = fmaxf(acc[mt][nt][2 * half + 1] + b1, 0.f);
                float hx, lx, hy, ly;
                hilo(ox, hx, lx);
                hilo(oy, hy, ly);
                Chi[(size_t)r * 64 + col / 2] = pack2(hx, hy);
                Clo[(size_t)r * 64 + col / 2] = pack2(lx, ly);
            }
        }
    }
}

// ================= launch =================
extern "C" void kernel_launch(void* const* d_in, const int* in_sizes, int n_in,
                              void* d_out, int out_size) {
    const float* x     = (const float*)d_in[0];
    const void*  ei    = d_in[1];
    const float* W_in  = (const float*)d_in[2];
    const float* b_in  = (const float*)d_in[3];
    const float* Wc    = (const float*)d_in[4];
    const float* bc    = (const float*)d_in[5];
    const float* W_out = (const float*)d_in[6];
    const float* b_out = (const float*)d_in[7];
    float* out = (float*)d_out;

    float* h;
    uint32_t *x0h, *x0l, *cath, *catl, *wh, *wl;
    cudaGetSymbolAddress((void**)&h, g_h);
    cudaGetSymbolAddress((void**)&x0h, g_x0h);
    cudaGetSymbolAddress((void**)&x0l, g_x0l);
    cudaGetSymbolAddress((void**)&cath, g_cath);
    cudaGetSymbolAddress((void**)&catl, g_catl);
    cudaGetSymbolAddress((void**)&wh, g_wh);
    cudaGetSymbolAddress((void**)&wl, g_wl);

    const int TB = 256;
    const int M = N_NODES;
    const int GB = (M + 127) / 128;   // 391

    // ---- CSR preprocessing ----
    detect_kernel<<<1, 256>>>(ei);
    deg_init_kernel<<<(N_NODES + TB - 1) / TB, TB>>>();
    convert_count_kernel<<<(N_EDGES + TB - 1) / TB, TB>>>(ei);
    scan1_kernel<<<NBLK, SCAN_B>>>();
    scan2_kernel<<<1, SCAN_B>>>();
    scan3_kernel<<<NBLK, SCAN_B>>>();
    fill_kernel<<<(N_EDGES + TB - 1) / TB, TB>>>();

    // ---- weight split ----
    split_w_kernel<<<(WU_TOT + TB - 1) / TB, TB>>>(W_in, Wc, W_out);

    // ---- input projection + relu (split output) ----
    mma_gemm_inproj<<<GB, 256>>>(x, wh + WU_IN, wl + WU_IN, b_in, x0h, x0l, M);

    // ---- conv layers ----
    const int gthreads = N_NODES * 32;
    for (int L = 0; L < N_LAYERS; L++) {
        const uint32_t* Ah = (L == 0) ? x0h : (cath + (size_t)(L - 1) * 64);
        const uint32_t* Al = (L == 0) ? x0l : (catl + (size_t)(L - 1) * 64);
        int lda_u = (L == 0) ? 64 : CATU;
        mma_gemm_split<128, false><<<GB, 256>>>(
            Ah, Al, lda_u,
            wh + WU_C + (size_t)L * 8192, wl + WU_C + (size_t)L * 8192,
            bc + (size_t)L * HID,
            h, HID, nullptr, nullptr, 0, M, HID);
        gather_kernel<<<(gthreads + TB - 1) / TB, TB>>>(h, cath + (size_t)L * 64, catl + (size_t)L * 64);
    }

    // ---- final projection: K=512, NN=64, fp32 out ----
    mma_gemm_split<64, false><<<GB, 256>>>(
        cath, catl, CATU,
        wh + WU_OUT, wl + WU_OUT,
        b_out,
        out, OUT_CH, nullptr, nullptr, 0, M, CATW);
}

// round 6
// speedup vs baseline: 2.7870x; 1.0853x over previous
#include <cuda_runtime.h>
#include <cuda_bf16.h>
#include <math.h>
#include <stdint.h>

#define N_NODES 50000
#define N_EDGES 800000
#define HID     128
#define OUT_CH  64
#define N_LAYERS 4
#define CATW    (HID * N_LAYERS)   // 512
#define CATU    (CATW / 2)         // 256 u32 per row

// weight regions in split-u32 space
#define WU_IN   0
#define WU_C    8192
#define WU_OUT  (WU_C + 4 * 8192)
#define WU_TOT  (WU_OUT + 16384)

// ================= device scratch =================
__device__ __align__(16) uint32_t g_x0h[(size_t)N_NODES * HID / 2];
__device__ __align__(16) uint32_t g_x0l[(size_t)N_NODES * HID / 2];
__device__ float  g_h[(size_t)N_NODES * HID];
__device__ __align__(16) uint32_t g_cath[(size_t)N_NODES * CATU];
__device__ __align__(16) uint32_t g_catl[(size_t)N_NODES * CATU];
__device__ __align__(16) uint32_t g_wh[WU_TOT];
__device__ __align__(16) uint32_t g_wl[WU_TOT];
__device__ int    g_degi[N_NODES];
__device__ int    g_src[N_EDGES];
__device__ int    g_dst[N_EDGES];
__device__ int    g_off[N_NODES + 1];
__device__ int    g_cur[N_NODES];
__device__ float2 g_adj[N_EDGES];
__device__ int    g_is64;

#define SCAN_B 256
#define NBLK ((N_NODES + SCAN_B - 1) / SCAN_B)
__device__ int g_bsum[NBLK];

// ================= helpers =================
__device__ __forceinline__ uint32_t pack2(float lo_elem, float hi_elem) {
    __nv_bfloat162 t = __floats2bfloat162_rn(lo_elem, hi_elem);
    return *(uint32_t*)&t;
}
__device__ __forceinline__ void hilo(float x, float& h, float& l) {
    float hf = __bfloat162float(__float2bfloat16_rn(x));
    h = hf;
    l = x - hf;
}
__device__ __forceinline__ void mma16816(float* c, const uint32_t* a, const uint32_t* b) {
    asm volatile(
        "mma.sync.aligned.m16n8k16.row.col.f32.bf16.bf16.f32 "
        "{%0,%1,%2,%3}, {%4,%5,%6,%7}, {%8,%9}, {%0,%1,%2,%3};"
        : "+f"(c[0]), "+f"(c[1]), "+f"(c[2]), "+f"(c[3])
        : "r"(a[0]), "r"(a[1]), "r"(a[2]), "r"(a[3]), "r"(b[0]), "r"(b[1]));
}
__device__ __forceinline__ uint32_t smem_u32(const void* p) {
    uint32_t a;
    asm("{ .reg .u64 t; cvta.to.shared.u64 t, %1; cvt.u32.u64 %0, t; }" : "=r"(a) : "l"(p));
    return a;
}
__device__ __forceinline__ void cp_async16(uint32_t saddr, const void* gptr, bool pred) {
    int sz = pred ? 16 : 0;
    asm volatile("cp.async.cg.shared.global [%0], [%1], 16, %2;"
                 :: "r"(saddr), "l"(gptr), "r"(sz));
}
#define CP_COMMIT() asm volatile("cp.async.commit_group;" ::: "memory")
#define CP_WAIT(n)  asm volatile("cp.async.wait_group %0;" :: "n"(n) : "memory")

// ================= preprocessing =================
__global__ void detect_kernel(const void* ei) {
    const long long* p = (const long long*)ei;
    int bad = 0;
    for (int i = threadIdx.x; i < 1024; i += blockDim.x) {
        long long v = p[i];
        if (v < 0 || v >= (long long)N_NODES) bad = 1;
    }
    bad = __syncthreads_or(bad);
    if (threadIdx.x == 0) g_is64 = bad ? 0 : 1;
}
__global__ void deg_init_kernel() {
    int v = blockIdx.x * blockDim.x + threadIdx.x;
    if (v < N_NODES) g_degi[v] = 1;
}
__global__ void convert_count_kernel(const void* ei) {
    int e = blockIdx.x * blockDim.x + threadIdx.x;
    if (e >= N_EDGES) return;
    int s, d;
    if (g_is64) {
        const long long* p = (const long long*)ei;
        s = (int)p[e];
        d = (int)p[N_EDGES + e];
    } else {
        const int* p = (const int*)ei;
        s = p[e];
        d = p[N_EDGES + e];
    }
    g_src[e] = s;
    g_dst[e] = d;
    atomicAdd(&g_degi[d], 1);
}
__global__ void scan1_kernel() {
    __shared__ int s[SCAN_B];
    int t = threadIdx.x;
    int v = blockIdx.x * SCAN_B + t;
    s[t] = (v < N_NODES) ? (g_degi[v] - 1) : 0;
    __syncthreads();
    for (int off = SCAN_B / 2; off > 0; off >>= 1) {
        if (t < off) s[t] += s[t + off];
        __syncthreads();
    }
    if (t == 0) g_bsum[blockIdx.x] = s[0];
}
__global__ void scan2_kernel() {
    __shared__ int s[SCAN_B];
    int t = threadIdx.x;
    int v = (t < NBLK) ? g_bsum[t] : 0;
    s[t] = v;
    __syncthreads();
    for (int off = 1; off < SCAN_B; off <<= 1) {
        int a = (t >= off) ? s[t - off] : 0;
        __syncthreads();
        s[t] += a;
        __syncthreads();
    }
    if (t < NBLK) g_bsum[t] = s[t] - v;
    if (t == NBLK - 1) g_off[N_NODES] = s[t];
}
__global__ void scan3_kernel() {
    __shared__ int s[SCAN_B];
    int t = threadIdx.x;
    int v = blockIdx.x * SCAN_B + t;
    int d = (v < N_NODES) ? (g_degi[v] - 1) : 0;
    s[t] = d;
    __syncthreads();
    for (int off = 1; off < SCAN_B; off <<= 1) {
        int a = (t >= off) ? s[t - off] : 0;
        __syncthreads();
        s[t] += a;
        __syncthreads();
    }
    if (v < N_NODES) {
        g_off[v] = g_bsum[blockIdx.x] + s[t] - d;
        g_cur[v] = 0;
    }
}
__global__ void fill_kernel() {
    int e = blockIdx.x * blockDim.x + threadIdx.x;
    if (e >= N_EDGES) return;
    int s = g_src[e], d = g_dst[e];
    int pos = g_off[d] + atomicAdd(&g_cur[d], 1);
    float nm = rsqrtf((float)g_degi[s] * (float)g_degi[d]);
    g_adj[pos] = make_float2(__int_as_float(s), nm);
}

// ================= weight split =================
__global__ void split_w_kernel(const float* __restrict__ W_in,
                               const float* __restrict__ Wc,
                               const float* __restrict__ W_out) {
    int t = blockIdx.x * blockDim.x + threadIdx.x;
    if (t >= WU_TOT) return;
    const float* src;
    int rt;
    if (t < WU_C) { src = W_in; rt = t; }
    else if (t < WU_OUT) { src = Wc; rt = t - WU_C; }
    else { src = W_out; rt = t - WU_OUT; }
    float a = src[2 * rt], b = src[2 * rt + 1];
    float ha, la, hb, lb;
    hilo(a, ha, la);
    hilo(b, hb, lb);
    g_wh[t] = pack2(ha, hb);
    g_wl[t] = pack2(la, lb);
}

// ================= pipelined bf16x2-split GEMM (cp.async double buffer) =================
// C[M, NN] = A[M, K] @ W[NN, K]^T + bias (fp32 out).
#define PADU 20

template <int NN>
__global__ void __launch_bounds__(256) mma_gemm_pipe(
    const uint32_t* __restrict__ Ah, const uint32_t* __restrict__ Al, int lda_u,
    const uint32_t* __restrict__ Bh, const uint32_t* __restrict__ Bl,
    const float* __restrict__ bias,
    float* __restrict__ Cf, int ldc,
    int M, int K)
{
    extern __shared__ uint32_t dyn[];
    // per-buffer layout (u32): [Ahi 128*PADU][Alo 128*PADU][Bhi NN*PADU][Blo NN*PADU]
    constexpr int OA_LO = 128 * PADU;
    constexpr int OB_HI = 2 * 128 * PADU;
    constexpr int OB_LO = OB_HI + NN * PADU;
    constexpr int BUF_U = OB_LO + NN * PADU;

    const int tid = threadIdx.x;
    const int wid = tid >> 5;
    const int lane = tid & 31;
    const int gr = lane >> 2;
    const int gc = lane & 3;
    const int warp_m = wid >> 1;
    const int warp_n = wid & 1;
    const int m0 = blockIdx.x * 128;
    constexpr int NT = NN / 16;

    const uint32_t sbase = smem_u32(dyn);
    const int Ku = K >> 1;
    const int chunks = K >> 5;

    float acc[2][NT][4];
#pragma unroll
    for (int mt = 0; mt < 2; mt++)
#pragma unroll
        for (int nt = 0; nt < NT; nt++)
#pragma unroll
            for (int j = 0; j < 4; j++) acc[mt][nt][j] = 0.0f;

    // ---- staging (cp.async, all 16B) ----
    auto stage = [&](int c, int buf) {
        const int k0u = c << 4;
        const uint32_t sb = sbase + (uint32_t)buf * BUF_U * 4;
        // A: 512 16B-units for hi, 512 for lo
#pragma unroll
        for (int it = 0; it < 2; it++) {
            int idx = tid + it * 256;
            int row = idx >> 2, j = idx & 3;
            bool ok = (m0 + row < M);
            size_t go = ok ? ((size_t)(m0 + row) * lda_u + k0u + j * 4) : 0;
            uint32_t so = (uint32_t)(row * PADU + j * 4) * 4;
            cp_async16(sb + so, Ah + go, ok);
            cp_async16(sb + OA_LO * 4 + so, Al + go, ok);
        }
        // B: NN*4 16B-units each
#pragma unroll
        for (int it = 0; it < NN / 64; it++) {
            int idx = tid + it * 256;
            int row = idx >> 2, j = idx & 3;
            size_t go = (size_t)row * Ku + k0u + j * 4;
            uint32_t so = (uint32_t)(row * PADU + j * 4) * 4;
            cp_async16(sb + OB_HI * 4 + so, Bh + go, true);
            cp_async16(sb + OB_LO * 4 + so, Bl + go, true);
        }
        CP_COMMIT();
    };

    stage(0, 0);

    for (int c = 0; c < chunks; c++) {
        const int cur = c & 1;
        if (c + 1 < chunks) {
            stage(c + 1, cur ^ 1);
            CP_WAIT(1);
        } else {
            CP_WAIT(0);
        }
        __syncthreads();

        const uint32_t* sAh = dyn + cur * BUF_U;
        const uint32_t* sAl = sAh + OA_LO;
        const uint32_t* sBh = dyn + cur * BUF_U + OB_HI;
        const uint32_t* sBl = dyn + cur * BUF_U + OB_LO;

#pragma unroll
        for (int s = 0; s < 2; s++) {
            const int kc = s * 8 + gc;
            uint32_t ah[2][4], al[2][4];
#pragma unroll
            for (int mt = 0; mt < 2; mt++) {
                int r = warp_m * 32 + mt * 16 + gr;
                ah[mt][0] = sAh[r * PADU + kc];
                ah[mt][1] = sAh[(r + 8) * PADU + kc];
                ah[mt][2] = sAh[r * PADU + kc + 4];
                ah[mt][3] = sAh[(r + 8) * PADU + kc + 4];
                al[mt][0] = sAl[r * PADU + kc];
                al[mt][1] = sAl[(r + 8) * PADU + kc];
                al[mt][2] = sAl[r * PADU + kc + 4];
                al[mt][3] = sAl[(r + 8) * PADU + kc + 4];
            }
#pragma unroll
            for (int nt = 0; nt < NT; nt++) {
                int n = warp_n * (NN / 2) + nt * 8 + gr;
                uint32_t bh[2], bl[2];
                bh[0] = sBh[n * PADU + kc];
                bh[1] = sBh[n * PADU + kc + 4];
                bl[0] = sBl[n * PADU + kc];
                bl[1] = sBl[n * PADU + kc + 4];
#pragma unroll
                for (int mt = 0; mt < 2; mt++) {
                    mma16816(acc[mt][nt], ah[mt], bh);
                    mma16816(acc[mt][nt], ah[mt], bl);
                    mma16816(acc[mt][nt], al[mt], bh);
                }
            }
        }
        __syncthreads();
    }

    // epilogue (fp32)
#pragma unroll
    for (int mt = 0; mt < 2; mt++) {
#pragma unroll
        for (int nt = 0; nt < NT; nt++) {
            int col = warp_n * (NN / 2) + nt * 8 + 2 * gc;
            float b0 = __ldg(bias + col);
            float b1 = __ldg(bias + col + 1);
#pragma unroll
            for (int half = 0; half < 2; half++) {
                int r = m0 + warp_m * 32 + mt * 16 + gr + half * 8;
                if (r >= M) continue;
                float2 o = make_float2(acc[mt][nt][2 * half + 0] + b0,
                                       acc[mt][nt][2 * half + 1] + b1);
                *(float2*)(Cf + (size_t)r * ldc + col) = o;
            }
        }
    }
}

// ================= input-projection GEMM (fp32 A, converting staging, split epilogue) =================
__global__ void __launch_bounds__(256) mma_gemm_inproj(
    const float* __restrict__ A,
    const uint32_t* __restrict__ Bh, const uint32_t* __restrict__ Bl,
    const float* __restrict__ bias,
    uint32_t* __restrict__ Chi, uint32_t* __restrict__ Clo,
    int M)
{
    constexpr int NN = 128;
    constexpr int K = 128;
    __shared__ uint32_t sAh[128 * PADU];
    __shared__ uint32_t sAl[128 * PADU];
    __shared__ uint32_t sBh[NN * PADU];
    __shared__ uint32_t sBl[NN * PADU];

    const int tid = threadIdx.x;
    const int wid = tid >> 5;
    const int lane = tid & 31;
    const int gr = lane >> 2;
    const int gc = lane & 3;
    const int warp_m = wid >> 1;
    const int warp_n = wid & 1;
    const int m0 = blockIdx.x * 128;
    constexpr int NT = NN / 16;

    float acc[2][NT][4];
#pragma unroll
    for (int mt = 0; mt < 2; mt++)
#pragma unroll
        for (int nt = 0; nt < NT; nt++)
#pragma unroll
            for (int j = 0; j < 4; j++) acc[mt][nt][j] = 0.0f;

    for (int c = 0; c < 4; c++) {
        const int k0 = c << 5;
        const int k0u = c << 4;
#pragma unroll
        for (int it = 0; it < 4; it++) {
            int idx = tid + it * 256;
            int row = idx >> 3, q = idx & 7;
            float4 v = make_float4(0.f, 0.f, 0.f, 0.f);
            if (m0 + row < M)
                v = *(const float4*)(A + (size_t)(m0 + row) * K + k0 + q * 4);
            float h0, h1, h2, h3, l0, l1, l2, l3;
            hilo(v.x, h0, l0); hilo(v.y, h1, l1); hilo(v.z, h2, l2); hilo(v.w, h3, l3);
            int base = row * PADU + 2 * q;
            sAh[base + 0] = pack2(h0, h1);
            sAh[base + 1] = pack2(h2, h3);
            sAl[base + 0] = pack2(l0, l1);
            sAl[base + 1] = pack2(l2, l3);
        }
#pragma unroll
        for (int it = 0; it < 2; it++) {
            int idx = tid + it * 256;
            int row = idx >> 2, j = idx & 3;
            uint4 vh = *(const uint4*)(Bh + (size_t)row * 64 + k0u + j * 4);
            uint4 vl = *(const uint4*)(Bl + (size_t)row * 64 + k0u + j * 4);
            *(uint4*)&sBh[row * PADU + j * 4] = vh;
            *(uint4*)&sBl[row * PADU + j * 4] = vl;
        }
        __syncthreads();

#pragma unroll
        for (int s = 0; s < 2; s++) {
            const int kc = s * 8 + gc;
            uint32_t ah[2][4], al[2][4];
#pragma unroll
            for (int mt = 0; mt < 2; mt++) {
                int r = warp_m * 32 + mt * 16 + gr;
                ah[mt][0] = sAh[r * PADU + kc];
                ah[mt][1] = sAh[(r + 8) * PADU + kc];
                ah[mt][2] = sAh[r * PADU + kc + 4];
                ah[mt][3] = sAh[(r + 8) * PADU + kc + 4];
                al[mt][0] = sAl[r * PADU + kc];
                al[mt][1] = sAl[(r + 8) * PADU + kc];
                al[mt][2] = sAl[r * PADU + kc + 4];
                al[mt][3] = sAl[(r + 8) * PADU + kc + 4];
            }
#pragma unroll
            for (int nt = 0; nt < NT; nt++) {
                int n = warp_n * (NN / 2) + nt * 8 + gr;
                uint32_t bh[2], bl[2];
                bh[0] = sBh[n * PADU + kc];
                bh[1] = sBh[n * PADU + kc + 4];
                bl[0] = sBl[n * PADU + kc];
                bl[1] = sBl[n * PADU + kc + 4];
#pragma unroll
                for (int mt = 0; mt < 2; mt++) {
                    mma16816(acc[mt][nt], ah[mt], bh);
                    mma16816(acc[mt][nt], ah[mt], bl);
                    mma16816(acc[mt][nt], al[mt], bh);
                }
            }
        }
        __syncthreads();
    }

#pragma unroll
    for (int mt = 0; mt < 2; mt++) {
#pragma unroll
        for (int nt = 0; nt < NT; nt++) {
            int col = warp_n * (NN / 2) + nt * 8 + 2 * gc;
            float b0 = __ldg(bias + col);
            float b1 = __ldg(bias + col + 1);
#pragma unroll
            for (int half = 0; half < 2; half++) {
                int r = m0 + warp_m * 32 + mt * 16 + gr + half * 8;
                if (r >= M) continue;
                float ox = fmaxf(acc[mt][nt][2 * half + 0] + b0, 0.f);
                float oy = fmaxf(acc[mt][nt][2 * half + 1] + b1, 0.f);
                float hx, lx, hy, ly;
                hilo(ox, hx, lx);
                hilo(oy, hy, ly);
                Chi[(size_t)r * 64 + col / 2] = pack2(hx, hy);
                Clo[(size_t)r * 64 + col / 2] = pack2(lx, ly);
            }
        }
    }
}

// ================= fused aggregation: gather + self-loop + ReLU + split =================
__global__ void gather_kernel(const float* __restrict__ h,
                              uint32_t* __restrict__ cat_hi,
                              uint32_t* __restrict__ cat_lo) {
    int w = (blockIdx.x * blockDim.x + threadIdx.x) >> 5;
    int lane = threadIdx.x & 31;
    if (w >= N_NODES) return;

    int beg = g_off[w];
    int end = g_off[w + 1];
    float dinv = 1.0f / (float)(end - beg + 1);

    float4 acc = ((const float4*)(h + (size_t)w * HID))[lane];
    acc.x *= dinv; acc.y *= dinv; acc.z *= dinv; acc.w *= dinv;

    int i = beg;
    for (; i + 4 <= end; i += 4) {
        float2 p0 = g_adj[i + 0];
        float2 p1 = g_adj[i + 1];
        float2 p2 = g_adj[i + 2];
        float2 p3 = g_adj[i + 3];
        float4 v0 = ((const float4*)(h + (size_t)__float_as_int(p0.x) * HID))[lane];
        float4 v1 = ((const float4*)(h + (size_t)__float_as_int(p1.x) * HID))[lane];
        float4 v2 = ((const float4*)(h + (size_t)__float_as_int(p2.x) * HID))[lane];
        float4 v3 = ((const float4*)(h + (size_t)__float_as_int(p3.x) * HID))[lane];
        acc.x += v0.x * p0.y; acc.y += v0.y * p0.y; acc.z += v0.z * p0.y; acc.w += v0.w * p0.y;
        acc.x += v1.x * p1.y; acc.y += v1.y * p1.y; acc.z += v1.z * p1.y; acc.w += v1.w * p1.y;
        acc.x += v2.x * p2.y; acc.y += v2.y * p2.y; acc.z += v2.z * p2.y; acc.w += v2.w * p2.y;
        acc.x += v3.x * p3.y; acc.y += v3.y * p3.y; acc.z += v3.z * p3.y; acc.w += v3.w * p3.y;
    }
    for (; i < end; i++) {
        float2 p = g_adj[i];
        float4 v = ((const float4*)(h + (size_t)__float_as_int(p.x) * HID))[lane];
        acc.x += v.x * p.y; acc.y += v.y * p.y; acc.z += v.z * p.y; acc.w += v.w * p.y;
    }

    acc.x = fmaxf(acc.x, 0.f);
    acc.y = fmaxf(acc.y, 0.f);
    acc.z = fmaxf(acc.z, 0.f);
    acc.w = fmaxf(acc.w, 0.f);

    float h0, l0, h1, l1, h2, l2, h3, l3;
    hilo(acc.x, h0, l0);
    hilo(acc.y, h1, l1);
    hilo(acc.z, h2, l2);
    hilo(acc.w, h3, l3);
    uint2 uhi = make_uint2(pack2(h0, h1), pack2(h2, h3));
    uint2 ulo = make_uint2(pack2(l0, l1), pack2(l2, l3));
    *(uint2*)(cat_hi + (size_t)w * CATU + 2 * lane) = uhi;
    *(uint2*)(cat_lo + (size_t)w * CATU + 2 * lane) = ulo;
}

// ================= launch =================
extern "C" void kernel_launch(void* const* d_in, const int* in_sizes, int n_in,
                              void* d_out, int out_size) {
    const float* x     = (const float*)d_in[0];
    const void*  ei    = d_in[1];
    const float* W_in  = (const float*)d_in[2];
    const float* b_in  = (const float*)d_in[3];
    const float* Wc    = (const float*)d_in[4];
    const float* bc    = (const float*)d_in[5];
    const float* W_out = (const float*)d_in[6];
    const float* b_out = (const float*)d_in[7];
    float* out = (float*)d_out;

    float* h;
    uint32_t *x0h, *x0l, *cath, *catl, *wh, *wl;
    cudaGetSymbolAddress((void**)&h, g_h);
    cudaGetSymbolAddress((void**)&x0h, g_x0h);
    cudaGetSymbolAddress((void**)&x0l, g_x0l);
    cudaGetSymbolAddress((void**)&cath, g_cath);
    cudaGetSymbolAddress((void**)&catl, g_catl);
    cudaGetSymbolAddress((void**)&wh, g_wh);
    cudaGetSymbolAddress((void**)&wl, g_wl);

    // dynamic smem sizes: 2 buffers of [A(2*128*PADU) + B(2*NN*PADU)] u32
    const int SM128 = 2 * (2 * 128 * PADU + 2 * 128 * PADU) * 4;   // 81920
    const int SM64  = 2 * (2 * 128 * PADU + 2 * 64 * PADU) * 4;    // 61440
    cudaFuncSetAttribute(mma_gemm_pipe<128>, cudaFuncAttributeMaxDynamicSharedMemorySize, SM128);
    cudaFuncSetAttribute(mma_gemm_pipe<64>,  cudaFuncAttributeMaxDynamicSharedMemorySize, SM64);

    const int TB = 256;
    const int M = N_NODES;
    const int GB = (M + 127) / 128;

    // ---- CSR preprocessing ----
    detect_kernel<<<1, 256>>>(ei);
    deg_init_kernel<<<(N_NODES + TB - 1) / TB, TB>>>();
    convert_count_kernel<<<(N_EDGES + TB - 1) / TB, TB>>>(ei);
    scan1_kernel<<<NBLK, SCAN_B>>>();
    scan2_kernel<<<1, SCAN_B>>>();
    scan3_kernel<<<NBLK, SCAN_B>>>();
    fill_kernel<<<(N_EDGES + TB - 1) / TB, TB>>>();

    // ---- weight split ----
    split_w_kernel<<<(WU_TOT + TB - 1) / TB, TB>>>(W_in, Wc, W_out);

    // ---- input projection + relu (split output) ----
    mma_gemm_inproj<<<GB, 256>>>(x, wh + WU_IN, wl + WU_IN, b_in, x0h, x0l, M);

    // ---- conv layers ----
    const int gthreads = N_NODES * 32;
    for (int L = 0; L < N_LAYERS; L++) {
        const uint32_t* Ah = (L == 0) ? x0h : (cath + (size_t)(L - 1) * 64);
        const uint32_t* Al = (L == 0) ? x0l : (catl + (size_t)(L - 1) * 64);
        int lda_u = (L == 0) ? 64 : CATU;
        mma_gemm_pipe<128><<<GB, 256, SM128>>>(
            Ah, Al, lda_u,
            wh + WU_C + (size_t)L * 8192, wl + WU_C + (size_t)L * 8192,
            bc + (size_t)L * HID,
            h, HID, M, HID);
        gather_kernel<<<(gthreads + TB - 1) / TB, TB>>>(h, cath + (size_t)L * 64, catl + (size_t)L * 64);
    }

    // ---- final projection: K=512, NN=64, fp32 out ----
    mma_gemm_pipe<64><<<GB, 256, SM64>>>(
        cath, catl, CATU,
        wh + WU_OUT, wl + WU_OUT,
        b_out,
        out, OUT_CH, M, CATW);
}